// round 13
// baseline (speedup 1.0000x reference)
#include <cuda_runtime.h>
#include <cuda_fp16.h>
#include <cstdint>
#include <cstddef>

// Problem dims
#define INF    4096
#define OUTF   11008
#define MTOT   4096     // 2*2048
#define GROUPS 32

// GEMM tiling (validated best: 128x128, 256 thr, 2 CTAs/SM)
#define BM     128
#define BN     128
#define BK     64                  // halves per stage (128B rows -> SW128 atom)
#define NCHUNK (INF / BK)          // 64
#define NSTAGE 3

#define STAGE_BYTES 32768          // 16KB A + 16KB B
#define SMEM_BYTES  (NSTAGE * STAGE_BYTES)   // 98304 -> 2 CTAs/SM

// Prep kernel grid split
#define CONVX_BLOCKS   16384       // 4,194,304 float4 vecs / 256
#define DEQ_BLOCKS     (OUTF / 8)  // 1376 blocks; each owns 8 n x 512 packed rows
#define PREP_BLOCKS    (CONVX_BLOCKS + DEQ_BLOCKS)

// Scratch (static __device__ arrays; no allocation APIs used)
__device__ __align__(16) __half g_Wt[(size_t)OUTF * INF];   // W^T, [N, K] K-major f16
__device__ __align__(16) __half g_X[(size_t)MTOT * INF];    // x in f16

// ---------------- helpers ----------------
__device__ __forceinline__ uint32_t smem_u32(const void* p) {
    uint32_t a;
    asm("{ .reg .u64 t; cvta.to.shared.u64 t, %1; cvt.u32.u64 %0, t; }" : "=r"(a) : "l"(p));
    return a;
}
__device__ __forceinline__ uint32_t sw128(uint32_t off) {
    return off ^ ((off >> 3) & 0x70);
}
__device__ __forceinline__ void cp16(uint32_t dst, const void* src) {
    asm volatile("cp.async.cg.shared.global [%0], [%1], 16;" :: "r"(dst), "l"(src));
}
#define CP_COMMIT() asm volatile("cp.async.commit_group;" ::: "memory")
#define CP_WAIT(n)  asm volatile("cp.async.wait_group %0;" :: "n"(n) : "memory")

// volatile: must stay ordered vs barriers / cp.async (touches shared memory)
__device__ __forceinline__ void ldmx4(uint32_t& r0, uint32_t& r1, uint32_t& r2, uint32_t& r3,
                                      uint32_t addr) {
    asm volatile("ldmatrix.sync.aligned.m8n8.x4.shared.b16 {%0,%1,%2,%3}, [%4];"
                 : "=r"(r0), "=r"(r1), "=r"(r2), "=r"(r3) : "r"(addr));
}
// NON-volatile: pure register dataflow; ptxas may interleave MMAs with later LDSMs
__device__ __forceinline__ void mma16816(float* c, const uint32_t* a, const uint32_t* b) {
    asm("mma.sync.aligned.m16n8k16.row.col.f32.f16.f16.f32 "
        "{%0,%1,%2,%3}, {%4,%5,%6,%7}, {%8,%9}, {%0,%1,%2,%3};"
        : "+f"(c[0]), "+f"(c[1]), "+f"(c[2]), "+f"(c[3])
        : "r"(a[0]), "r"(a[1]), "r"(a[2]), "r"(a[3]), "r"(b[0]), "r"(b[1]));
}

// ---------------- Kernel 1: fused prep ----------------
// b < CONVX_BLOCKS : x fp32 -> f16
// else             : dequant 8-n slice of qweight -> W^T f16 (sector-perfect reads,
//                    smem transpose with pad-9 stride, coalesced writes)
__global__ void __launch_bounds__(256) prep_kernel(const float* __restrict__ x,
                                                   const int* __restrict__ qw,
                                                   const float* __restrict__ scales,
                                                   const float* __restrict__ zeros) {
    __shared__ int s[512 * 9];      // 18KB, row stride 9 ints (9 coprime 32 -> no conflicts)
    int b = blockIdx.x;
    int tid = threadIdx.x;
    if (b < CONVX_BLOCKS) {
        size_t idx = (size_t)b * 256 + tid;
        float4 v = reinterpret_cast<const float4*>(x)[idx];
        __half2 a = __floats2half2_rn(v.x, v.y);
        __half2 bb = __floats2half2_rn(v.z, v.w);
        uint2 u;
        u.x = *reinterpret_cast<uint32_t*>(&a);
        u.y = *reinterpret_cast<uint32_t*>(&bb);
        reinterpret_cast<uint2*>(g_X)[idx] = u;
    } else {
        const int n0 = (b - CONVX_BLOCKS) * 8;
        // load phase: qw tile [512 rows x 8 ints], int4 per 4-int half-row
#pragma unroll
        for (int i = 0; i < 4; i++) {
            int v = tid + 256 * i;        // 0..1023
            int row = v >> 1, half = v & 1;
            int4 q4 = *reinterpret_cast<const int4*>(qw + row * OUTF + n0 + half * 4);
            int* dst = s + row * 9 + half * 4;
            dst[0] = q4.x; dst[1] = q4.y; dst[2] = q4.z; dst[3] = q4.w;
        }
        __syncthreads();
        // compute phase: warp w handles n = n0 + w; lane l handles rows l + 32j
        const int w = tid >> 5, l = tid & 31;
        const int n = n0 + w;
        const float* sc = scales + n * GROUPS;
        const float* zr = zeros + n * GROUPS;
        __half* outp = g_Wt + (size_t)n * INF;
#pragma unroll
        for (int j = 0; j < 16; j++) {
            int r = l + 32 * j;
            int q = s[r * 9 + w];
            int g = r >> 4;
            float ss = sc[g];
            float zz = zr[g];
            __half2 h[4];
#pragma unroll
            for (int jj = 0; jj < 4; jj++) {
                float v0 = (float)((q >> (8 * jj)) & 0xF) * ss - zz;
                float v1 = (float)((q >> (8 * jj + 4)) & 0xF) * ss - zz;
                h[jj] = __floats2half2_rn(v0, v1);
            }
            *reinterpret_cast<uint4*>(outp + (size_t)r * 8) = *reinterpret_cast<uint4*>(h);
        }
    }
}

// ---------------- Kernel 2: pipelined HMMA GEMM, 128x128x64, 3 stages, occ=2 ----------------
// ks-head critical path shortened: afr[0] + B first, A[mt+1] prefetched under mt's MMAs.
__global__ void __launch_bounds__(256, 2) gemm_kernel(const float* __restrict__ bias,
                                                      float* __restrict__ out) {
    extern __shared__ char smem[];
    uint32_t sb = smem_u32(smem);
    const int tid = threadIdx.x;
    const int wid = tid >> 5, lid = tid & 31;
    const int wm = wid >> 2;          // 0..1  (M), 64-row warp tile
    const int wn = wid & 3;           // 0..3  (N), 32-col warp tile
    const int m0 = blockIdx.x * BM;
    const int n0 = blockIdx.y * BN;
    const int krev = wid & 1;         // odd warps walk ks in reverse (desync bursts)

    // cp.async fill offsets: row = tid/8 (+32*i), seg = tid%8
    const int frow = tid >> 3;
    const int fseg = tid & 7;
    uint32_t fsw[4];
#pragma unroll
    for (int i = 0; i < 4; i++) fsw[i] = sw128((frow + 32 * i) * 128 + fseg * 16);

    // global induction pointers (advance by BK per chunk; row offsets fold to immediates)
    const __half* pX = g_X  + (size_t)(m0 + frow) * INF + fseg * 8;
    const __half* pW = g_Wt + (size_t)(n0 + frow) * INF + fseg * 8;

    float acc[4][4][4];
#pragma unroll
    for (int i = 0; i < 4; i++)
#pragma unroll
        for (int j = 0; j < 4; j++)
#pragma unroll
            for (int k = 0; k < 4; k++) acc[i][j][k] = 0.0f;

    // ldmatrix lane decomposition (validated mapping)
    const int la = lid & 15, sa = lid >> 4;               // A: row-in-16, k-seg
    const int lbr = (lid & 7) + ((lid >> 4) << 3);        // B: n-in-16
    const int lbs = (lid >> 3) & 1;                       // B: k-seg
    uint32_t arow[4], amask[4], brow[2], bmask[2];
#pragma unroll
    for (int t = 0; t < 4; t++) {
        arow[t] = (uint32_t)(wm * 64 + t * 16 + la) * 128;
        amask[t] = (arow[t] >> 3) & 0x70;
    }
#pragma unroll
    for (int t = 0; t < 2; t++) {
        brow[t] = (uint32_t)(wn * 32 + t * 16 + lbr) * 128;
        bmask[t] = (brow[t] >> 3) & 0x70;
    }
    const uint32_t akp = (uint32_t)(sa * 16);
    const uint32_t bkp = (uint32_t)(lbs * 16);

    const uint32_t sbase0 = sb;
    const uint32_t sbase1 = sb + STAGE_BYTES;
    const uint32_t sbase2 = sb + 2 * STAGE_BYTES;

    // ---- prologue: stages 0..NSTAGE-2 ----
#pragma unroll
    for (int s = 0; s < NSTAGE - 1; s++) {
        uint32_t ab = sb + s * STAGE_BYTES;
        uint32_t bb = ab + 16384;
#pragma unroll
        for (int i = 0; i < 4; i++) {
            cp16(ab + fsw[i], pX + (size_t)32 * i * INF + s * BK);
            cp16(bb + fsw[i], pW + (size_t)32 * i * INF + s * BK);
        }
        CP_COMMIT();
    }

    // next-chunk load pointers (chunk index c+2)
    const __half* pXn = pX + (NSTAGE - 1) * BK;
    const __half* pWn = pW + (NSTAGE - 1) * BK;

    // ---- main loop: ONE __syncthreads per chunk; unroll 3 folds stage indices ----
#pragma unroll 3
    for (int c = 0; c < NCHUNK; c++) {
        CP_WAIT(NSTAGE - 2);
        __syncthreads();   // stage c ready; all warps done computing stage (c-1)

        const uint32_t ab = (c % 3 == 0) ? sbase0 : (c % 3 == 1) ? sbase1 : sbase2;
        const uint32_t bb = ab + 16384;
        const int nc = (c + NSTAGE - 1) % 3;
        const uint32_t nab = (nc == 0) ? sbase0 : (nc == 1) ? sbase1 : sbase2;
        const uint32_t nbb = nab + 16384;
        const bool donxt = c < NCHUNK - (NSTAGE - 1);

#pragma unroll
        for (int ksi = 0; ksi < 4; ksi++) {
            const int ks = krev ? (3 - ksi) : ksi;
            const uint32_t kA = (uint32_t)(ks * 32) + akp;
            const uint32_t kB = (uint32_t)(ks * 32) + bkp;
            uint32_t afr[4][4], bfr[4][2];

            // head: afr[0] + both B loads -> first MMA depends on 3 LDSMs, not 6
            ldmx4(afr[0][0], afr[0][1], afr[0][2], afr[0][3],
                  ab + arow[0] + (kA ^ amask[0]));
#pragma unroll
            for (int nb = 0; nb < 2; nb++) {
                uint32_t r0, r1, r2, r3;
                ldmx4(r0, r1, r2, r3, bb + brow[nb] + (kB ^ bmask[nb]));
                bfr[nb * 2 + 0][0] = r0; bfr[nb * 2 + 0][1] = r1;
                bfr[nb * 2 + 1][0] = r2; bfr[nb * 2 + 1][1] = r3;
            }
            // body: prefetch afr[mt+1] under mt's MMAs
#pragma unroll
            for (int mt = 0; mt < 4; mt++) {
                if (mt < 3)
                    ldmx4(afr[mt + 1][0], afr[mt + 1][1], afr[mt + 1][2], afr[mt + 1][3],
                          ab + arow[mt + 1] + (kA ^ amask[mt + 1]));
#pragma unroll
                for (int nt = 0; nt < 4; nt++)
                    mma16816(acc[mt][nt], afr[mt], bfr[nt]);
            }

            // after the first ks block: issue next chunk's fill (validated schedule)
            if (ksi == 0) {
                if (donxt) {
#pragma unroll
                    for (int i = 0; i < 4; i++) {
                        cp16(nab + fsw[i], pXn + (size_t)32 * i * INF);
                        cp16(nbb + fsw[i], pWn + (size_t)32 * i * INF);
                    }
                }
                CP_COMMIT();
            }
        }
        pXn += BK;
        pWn += BK;
    }

    // ---- epilogue: bias-fused float2 stores ----
    const int mrow = m0 + wm * 64 + (lid >> 2);
    const int ncol = n0 + wn * 32 + (lid & 3) * 2;
#pragma unroll
    for (int mt = 0; mt < 4; mt++) {
#pragma unroll
        for (int nt = 0; nt < 4; nt++) {
            int col = ncol + nt * 8;
            float2 bb = *reinterpret_cast<const float2*>(bias + col);
            int r0 = mrow + mt * 16;
            float2 v0 = {acc[mt][nt][0] + bb.x, acc[mt][nt][1] + bb.y};
            float2 v1 = {acc[mt][nt][2] + bb.x, acc[mt][nt][3] + bb.y};
            *reinterpret_cast<float2*>(out + (size_t)r0 * OUTF + col) = v0;
            *reinterpret_cast<float2*>(out + (size_t)(r0 + 8) * OUTF + col) = v1;
        }
    }
}

// ---------------- launch ----------------
extern "C" void kernel_launch(void* const* d_in, const int* in_sizes, int n_in,
                              void* d_out, int out_size) {
    const float* x      = (const float*)d_in[0];
    const int*   qw     = (const int*)d_in[1];
    const float* scales = (const float*)d_in[2];
    const float* zeros  = (const float*)d_in[3];
    const float* bias   = (const float*)d_in[4];
    float* out = (float*)d_out;

    cudaFuncSetAttribute(gemm_kernel, cudaFuncAttributeMaxDynamicSharedMemorySize, SMEM_BYTES);

    prep_kernel<<<PREP_BLOCKS, 256>>>(x, qw, scales, zeros);
    gemm_kernel<<<dim3(MTOT / BM, OUTF / BN), 256, SMEM_BYTES>>>(bias, out);
}

// round 14
// speedup vs baseline: 1.0020x; 1.0020x over previous
#include <cuda_runtime.h>
#include <cuda_fp16.h>
#include <cstdint>
#include <cstddef>

// Problem dims
#define INF    4096
#define OUTF   11008
#define MTOT   4096     // 2*2048
#define GROUPS 32

// GEMM tiling (validated best: 128x128, 256 thr, 2 CTAs/SM)
#define BM     128
#define BN     128
#define BK     64                  // halves per stage (128B rows -> SW128 atom)
#define NCHUNK (INF / BK)          // 64
#define NSTAGE 3

#define STAGE_BYTES 32768          // 16KB A + 16KB B
#define SMEM_BYTES  (NSTAGE * STAGE_BYTES)   // 98304 -> 2 CTAs/SM

// Prep kernel grid split
#define CONVX_BLOCKS   16384       // 4,194,304 float4 vecs / 256
#define DEQ_BLOCKS     (OUTF / 8)  // 1376 blocks; each owns 8 n x 512 packed rows
#define PREP_BLOCKS    (CONVX_BLOCKS + DEQ_BLOCKS)

// Scratch (static __device__ arrays; no allocation APIs used)
__device__ __align__(16) __half g_Wt[(size_t)OUTF * INF];   // W^T, [N, K] K-major f16
__device__ __align__(16) __half g_X[(size_t)MTOT * INF];    // x in f16

// ---------------- helpers ----------------
__device__ __forceinline__ uint32_t smem_u32(const void* p) {
    uint32_t a;
    asm("{ .reg .u64 t; cvta.to.shared.u64 t, %1; cvt.u32.u64 %0, t; }" : "=r"(a) : "l"(p));
    return a;
}
__device__ __forceinline__ uint32_t sw128(uint32_t off) {
    return off ^ ((off >> 3) & 0x70);
}
__device__ __forceinline__ void cp16(uint32_t dst, const void* src) {
    asm volatile("cp.async.cg.shared.global [%0], [%1], 16;" :: "r"(dst), "l"(src));
}
#define CP_COMMIT() asm volatile("cp.async.commit_group;" ::: "memory")
#define CP_WAIT(n)  asm volatile("cp.async.wait_group %0;" :: "n"(n) : "memory")

// volatile: must stay ordered vs barriers / cp.async (touches shared memory)
__device__ __forceinline__ void ldmx4(uint32_t& r0, uint32_t& r1, uint32_t& r2, uint32_t& r3,
                                      uint32_t addr) {
    asm volatile("ldmatrix.sync.aligned.m8n8.x4.shared.b16 {%0,%1,%2,%3}, [%4];"
                 : "=r"(r0), "=r"(r1), "=r"(r2), "=r"(r3) : "r"(addr));
}
// NON-volatile: pure register dataflow; ptxas may interleave MMAs with later LDSMs
__device__ __forceinline__ void mma16816(float* c, const uint32_t* a, const uint32_t* b) {
    asm("mma.sync.aligned.m16n8k16.row.col.f32.f16.f16.f32 "
        "{%0,%1,%2,%3}, {%4,%5,%6,%7}, {%8,%9}, {%0,%1,%2,%3};"
        : "+f"(c[0]), "+f"(c[1]), "+f"(c[2]), "+f"(c[3])
        : "r"(a[0]), "r"(a[1]), "r"(a[2]), "r"(a[3]), "r"(b[0]), "r"(b[1]));
}

// ---------------- Kernel 1: fused prep ----------------
// b < CONVX_BLOCKS : x fp32 -> f16
// else             : dequant 8-n slice of qweight -> W^T f16 (sector-perfect reads,
//                    smem transpose with pad-9 stride, coalesced writes)
__global__ void __launch_bounds__(256) prep_kernel(const float* __restrict__ x,
                                                   const int* __restrict__ qw,
                                                   const float* __restrict__ scales,
                                                   const float* __restrict__ zeros) {
    __shared__ int s[512 * 9];      // 18KB, row stride 9 ints (9 coprime 32 -> no conflicts)
    int b = blockIdx.x;
    int tid = threadIdx.x;
    if (b < CONVX_BLOCKS) {
        size_t idx = (size_t)b * 256 + tid;
        float4 v = reinterpret_cast<const float4*>(x)[idx];
        __half2 a = __floats2half2_rn(v.x, v.y);
        __half2 bb = __floats2half2_rn(v.z, v.w);
        uint2 u;
        u.x = *reinterpret_cast<uint32_t*>(&a);
        u.y = *reinterpret_cast<uint32_t*>(&bb);
        reinterpret_cast<uint2*>(g_X)[idx] = u;
    } else {
        const int n0 = (b - CONVX_BLOCKS) * 8;
        // load phase: qw tile [512 rows x 8 ints], int4 per 4-int half-row
#pragma unroll
        for (int i = 0; i < 4; i++) {
            int v = tid + 256 * i;        // 0..1023
            int row = v >> 1, half = v & 1;
            int4 q4 = *reinterpret_cast<const int4*>(qw + row * OUTF + n0 + half * 4);
            int* dst = s + row * 9 + half * 4;
            dst[0] = q4.x; dst[1] = q4.y; dst[2] = q4.z; dst[3] = q4.w;
        }
        __syncthreads();
        // compute phase: warp w handles n = n0 + w; lane l handles rows l + 32j
        const int w = tid >> 5, l = tid & 31;
        const int n = n0 + w;
        const float* sc = scales + n * GROUPS;
        const float* zr = zeros + n * GROUPS;
        __half* outp = g_Wt + (size_t)n * INF;
#pragma unroll
        for (int j = 0; j < 16; j++) {
            int r = l + 32 * j;
            int q = s[r * 9 + w];
            int g = r >> 4;
            float ss = sc[g];
            float zz = zr[g];
            __half2 h[4];
#pragma unroll
            for (int jj = 0; jj < 4; jj++) {
                float v0 = (float)((q >> (8 * jj)) & 0xF) * ss - zz;
                float v1 = (float)((q >> (8 * jj + 4)) & 0xF) * ss - zz;
                h[jj] = __floats2half2_rn(v0, v1);
            }
            *reinterpret_cast<uint4*>(outp + (size_t)r * 8) = *reinterpret_cast<uint4*>(h);
        }
    }
}

// ---------------- Kernel 2: pipelined HMMA GEMM, 128x128x64, 3 stages, occ=2 ----------------
// ks-head pipeline (R13) with compile-time ks (krev removed).
__global__ void __launch_bounds__(256, 2) gemm_kernel(const float* __restrict__ bias,
                                                      float* __restrict__ out) {
    extern __shared__ char smem[];
    uint32_t sb = smem_u32(smem);
    const int tid = threadIdx.x;
    const int wid = tid >> 5, lid = tid & 31;
    const int wm = wid >> 2;          // 0..1  (M), 64-row warp tile
    const int wn = wid & 3;           // 0..3  (N), 32-col warp tile
    const int m0 = blockIdx.x * BM;
    const int n0 = blockIdx.y * BN;

    // cp.async fill offsets: row = tid/8 (+32*i), seg = tid%8
    const int frow = tid >> 3;
    const int fseg = tid & 7;
    uint32_t fsw[4];
#pragma unroll
    for (int i = 0; i < 4; i++) fsw[i] = sw128((frow + 32 * i) * 128 + fseg * 16);

    // global induction pointers (advance by BK per chunk; row offsets fold to immediates)
    const __half* pX = g_X  + (size_t)(m0 + frow) * INF + fseg * 8;
    const __half* pW = g_Wt + (size_t)(n0 + frow) * INF + fseg * 8;

    float acc[4][4][4];
#pragma unroll
    for (int i = 0; i < 4; i++)
#pragma unroll
        for (int j = 0; j < 4; j++)
#pragma unroll
            for (int k = 0; k < 4; k++) acc[i][j][k] = 0.0f;

    // ldmatrix lane decomposition (validated mapping)
    const int la = lid & 15, sa = lid >> 4;               // A: row-in-16, k-seg
    const int lbr = (lid & 7) + ((lid >> 4) << 3);        // B: n-in-16
    const int lbs = (lid >> 3) & 1;                       // B: k-seg
    uint32_t arow[4], amask[4], brow[2], bmask[2];
#pragma unroll
    for (int t = 0; t < 4; t++) {
        arow[t] = (uint32_t)(wm * 64 + t * 16 + la) * 128;
        amask[t] = (arow[t] >> 3) & 0x70;
    }
#pragma unroll
    for (int t = 0; t < 2; t++) {
        brow[t] = (uint32_t)(wn * 32 + t * 16 + lbr) * 128;
        bmask[t] = (brow[t] >> 3) & 0x70;
    }
    const uint32_t akp = (uint32_t)(sa * 16);
    const uint32_t bkp = (uint32_t)(lbs * 16);

    const uint32_t sbase0 = sb;
    const uint32_t sbase1 = sb + STAGE_BYTES;
    const uint32_t sbase2 = sb + 2 * STAGE_BYTES;

    // ---- prologue: stages 0..NSTAGE-2 ----
#pragma unroll
    for (int s = 0; s < NSTAGE - 1; s++) {
        uint32_t ab = sb + s * STAGE_BYTES;
        uint32_t bb = ab + 16384;
#pragma unroll
        for (int i = 0; i < 4; i++) {
            cp16(ab + fsw[i], pX + (size_t)32 * i * INF + s * BK);
            cp16(bb + fsw[i], pW + (size_t)32 * i * INF + s * BK);
        }
        CP_COMMIT();
    }

    // next-chunk load pointers (chunk index c+2)
    const __half* pXn = pX + (NSTAGE - 1) * BK;
    const __half* pWn = pW + (NSTAGE - 1) * BK;

    // ---- main loop: ONE __syncthreads per chunk; unroll 3 folds stage indices ----
#pragma unroll 3
    for (int c = 0; c < NCHUNK; c++) {
        CP_WAIT(NSTAGE - 2);
        __syncthreads();   // stage c ready; all warps done computing stage (c-1)

        const uint32_t ab = (c % 3 == 0) ? sbase0 : (c % 3 == 1) ? sbase1 : sbase2;
        const uint32_t bb = ab + 16384;
        const int nc = (c + NSTAGE - 1) % 3;
        const uint32_t nab = (nc == 0) ? sbase0 : (nc == 1) ? sbase1 : sbase2;
        const uint32_t nbb = nab + 16384;
        const bool donxt = c < NCHUNK - (NSTAGE - 1);

#pragma unroll
        for (int ks = 0; ks < 4; ks++) {
            const uint32_t kA = (uint32_t)(ks * 32) + akp;
            const uint32_t kB = (uint32_t)(ks * 32) + bkp;
            uint32_t afr[4][4], bfr[4][2];

            // head: afr[0] + both B loads -> first MMA depends on 3 LDSMs, not 6
            ldmx4(afr[0][0], afr[0][1], afr[0][2], afr[0][3],
                  ab + arow[0] + (kA ^ amask[0]));
#pragma unroll
            for (int nb = 0; nb < 2; nb++) {
                uint32_t r0, r1, r2, r3;
                ldmx4(r0, r1, r2, r3, bb + brow[nb] + (kB ^ bmask[nb]));
                bfr[nb * 2 + 0][0] = r0; bfr[nb * 2 + 0][1] = r1;
                bfr[nb * 2 + 1][0] = r2; bfr[nb * 2 + 1][1] = r3;
            }
            // body: prefetch afr[mt+1] under mt's MMAs
#pragma unroll
            for (int mt = 0; mt < 4; mt++) {
                if (mt < 3)
                    ldmx4(afr[mt + 1][0], afr[mt + 1][1], afr[mt + 1][2], afr[mt + 1][3],
                          ab + arow[mt + 1] + (kA ^ amask[mt + 1]));
#pragma unroll
                for (int nt = 0; nt < 4; nt++)
                    mma16816(acc[mt][nt], afr[mt], bfr[nt]);
            }

            // after the first ks block: issue next chunk's fill (validated schedule)
            if (ks == 0) {
                if (donxt) {
#pragma unroll
                    for (int i = 0; i < 4; i++) {
                        cp16(nab + fsw[i], pXn + (size_t)32 * i * INF);
                        cp16(nbb + fsw[i], pWn + (size_t)32 * i * INF);
                    }
                }
                CP_COMMIT();
            }
        }
        pXn += BK;
        pWn += BK;
    }

    // ---- epilogue: bias-fused float2 stores ----
    const int mrow = m0 + wm * 64 + (lid >> 2);
    const int ncol = n0 + wn * 32 + (lid & 3) * 2;
#pragma unroll
    for (int mt = 0; mt < 4; mt++) {
#pragma unroll
        for (int nt = 0; nt < 4; nt++) {
            int col = ncol + nt * 8;
            float2 bb = *reinterpret_cast<const float2*>(bias + col);
            int r0 = mrow + mt * 16;
            float2 v0 = {acc[mt][nt][0] + bb.x, acc[mt][nt][1] + bb.y};
            float2 v1 = {acc[mt][nt][2] + bb.x, acc[mt][nt][3] + bb.y};
            *reinterpret_cast<float2*>(out + (size_t)r0 * OUTF + col) = v0;
            *reinterpret_cast<float2*>(out + (size_t)(r0 + 8) * OUTF + col) = v1;
        }
    }
}

// ---------------- launch ----------------
extern "C" void kernel_launch(void* const* d_in, const int* in_sizes, int n_in,
                              void* d_out, int out_size) {
    const float* x      = (const float*)d_in[0];
    const int*   qw     = (const int*)d_in[1];
    const float* scales = (const float*)d_in[2];
    const float* zeros  = (const float*)d_in[3];
    const float* bias   = (const float*)d_in[4];
    float* out = (float*)d_out;

    cudaFuncSetAttribute(gemm_kernel, cudaFuncAttributeMaxDynamicSharedMemorySize, SMEM_BYTES);

    prep_kernel<<<PREP_BLOCKS, 256>>>(x, qw, scales, zeros);
    gemm_kernel<<<dim3(MTOT / BM, OUTF / BN), 256, SMEM_BYTES>>>(bias, out);
}

// round 15
// speedup vs baseline: 1.0044x; 1.0023x over previous
#include <cuda_runtime.h>
#include <cuda_fp16.h>
#include <cstdint>
#include <cstddef>

// Problem dims
#define INF    4096
#define OUTF   11008
#define MTOT   4096     // 2*2048
#define GROUPS 32

// GEMM tiling (validated best: 128x128, 256 thr, 2 CTAs/SM)
#define BM     128
#define BN     128
#define BK     64                  // halves per stage (128B rows -> SW128 atom)
#define NCHUNK (INF / BK)          // 64
#define NSTAGE 3

#define STAGE_BYTES 32768          // 16KB A + 16KB B
#define SMEM_BYTES  (NSTAGE * STAGE_BYTES)   // 98304 -> 2 CTAs/SM

// Prep kernel grid: dequant blocks FIRST (longest-job-first), then convx
#define DEQ_BLOCKS     (OUTF / 8)  // 1376 blocks; each owns 8 n x 512 packed rows
#define CONVX_BLOCKS   8192        // 4,194,304 float4 vecs / (256 thr * 2 vec)
#define PREP_BLOCKS    (DEQ_BLOCKS + CONVX_BLOCKS)

// Scratch (static __device__ arrays; no allocation APIs used)
__device__ __align__(16) __half g_Wt[(size_t)OUTF * INF];   // W^T, [N, K] K-major f16
__device__ __align__(16) __half g_X[(size_t)MTOT * INF];    // x in f16

// ---------------- helpers ----------------
__device__ __forceinline__ uint32_t smem_u32(const void* p) {
    uint32_t a;
    asm("{ .reg .u64 t; cvta.to.shared.u64 t, %1; cvt.u32.u64 %0, t; }" : "=r"(a) : "l"(p));
    return a;
}
__device__ __forceinline__ uint32_t sw128(uint32_t off) {
    return off ^ ((off >> 3) & 0x70);
}
__device__ __forceinline__ void cp16(uint32_t dst, const void* src) {
    asm volatile("cp.async.cg.shared.global [%0], [%1], 16;" :: "r"(dst), "l"(src));
}
#define CP_COMMIT() asm volatile("cp.async.commit_group;" ::: "memory")
#define CP_WAIT(n)  asm volatile("cp.async.wait_group %0;" :: "n"(n) : "memory")

// volatile: must stay ordered vs barriers / cp.async (touches shared memory)
__device__ __forceinline__ void ldmx4(uint32_t& r0, uint32_t& r1, uint32_t& r2, uint32_t& r3,
                                      uint32_t addr) {
    asm volatile("ldmatrix.sync.aligned.m8n8.x4.shared.b16 {%0,%1,%2,%3}, [%4];"
                 : "=r"(r0), "=r"(r1), "=r"(r2), "=r"(r3) : "r"(addr));
}
// NON-volatile: pure register dataflow; ptxas may interleave MMAs with later LDSMs
__device__ __forceinline__ void mma16816(float* c, const uint32_t* a, const uint32_t* b) {
    asm("mma.sync.aligned.m16n8k16.row.col.f32.f16.f16.f32 "
        "{%0,%1,%2,%3}, {%4,%5,%6,%7}, {%8,%9}, {%0,%1,%2,%3};"
        : "+f"(c[0]), "+f"(c[1]), "+f"(c[2]), "+f"(c[3])
        : "r"(a[0]), "r"(a[1]), "r"(a[2]), "r"(a[3]), "r"(b[0]), "r"(b[1]));
}

// ---------------- Kernel 1: fused prep ----------------
// b < DEQ_BLOCKS : dequant 8-n slice of qweight -> W^T f16 (sector-perfect reads,
//                  smem transpose with pad-9 stride, coalesced writes).
//                  Heavy blocks scheduled FIRST so they overlap the convx swarm.
// else           : x fp32 -> f16, 2 float4 per thread (fewer waves, more MLP)
__global__ void __launch_bounds__(256) prep_kernel(const float* __restrict__ x,
                                                   const int* __restrict__ qw,
                                                   const float* __restrict__ scales,
                                                   const float* __restrict__ zeros) {
    __shared__ int s[512 * 9];      // 18KB, row stride 9 ints (9 coprime 32 -> no conflicts)
    int b = blockIdx.x;
    int tid = threadIdx.x;
    if (b < DEQ_BLOCKS) {
        const int n0 = b * 8;
        // load phase: qw tile [512 rows x 8 ints], int4 per 4-int half-row
#pragma unroll
        for (int i = 0; i < 4; i++) {
            int v = tid + 256 * i;        // 0..1023
            int row = v >> 1, half = v & 1;
            int4 q4 = *reinterpret_cast<const int4*>(qw + row * OUTF + n0 + half * 4);
            int* dst = s + row * 9 + half * 4;
            dst[0] = q4.x; dst[1] = q4.y; dst[2] = q4.z; dst[3] = q4.w;
        }
        __syncthreads();
        // compute phase: warp w handles n = n0 + w; lane l handles rows l + 32j
        const int w = tid >> 5, l = tid & 31;
        const int n = n0 + w;
        const float* sc = scales + n * GROUPS;
        const float* zr = zeros + n * GROUPS;
        __half* outp = g_Wt + (size_t)n * INF;
#pragma unroll
        for (int j = 0; j < 16; j++) {
            int r = l + 32 * j;
            int q = s[r * 9 + w];
            int g = r >> 4;
            float ss = sc[g];
            float zz = zr[g];
            __half2 h[4];
#pragma unroll
            for (int jj = 0; jj < 4; jj++) {
                float v0 = (float)((q >> (8 * jj)) & 0xF) * ss - zz;
                float v1 = (float)((q >> (8 * jj + 4)) & 0xF) * ss - zz;
                h[jj] = __floats2half2_rn(v0, v1);
            }
            *reinterpret_cast<uint4*>(outp + (size_t)r * 8) = *reinterpret_cast<uint4*>(h);
        }
    } else {
        size_t base = (size_t)(b - DEQ_BLOCKS) * 512 + tid;   // 2 vecs per thread
#pragma unroll
        for (int i = 0; i < 2; i++) {
            size_t idx = base + 256 * i;
            float4 v = reinterpret_cast<const float4*>(x)[idx];
            __half2 a = __floats2half2_rn(v.x, v.y);
            __half2 bb = __floats2half2_rn(v.z, v.w);
            uint2 u;
            u.x = *reinterpret_cast<uint32_t*>(&a);
            u.y = *reinterpret_cast<uint32_t*>(&bb);
            reinterpret_cast<uint2*>(g_X)[idx] = u;
        }
    }
}

// ---------------- Kernel 2: pipelined HMMA GEMM, 128x128x64, 3 stages, occ=2 ----------------
// (byte-identical to the validated round-14 744us version)
__global__ void __launch_bounds__(256, 2) gemm_kernel(const float* __restrict__ bias,
                                                      float* __restrict__ out) {
    extern __shared__ char smem[];
    uint32_t sb = smem_u32(smem);
    const int tid = threadIdx.x;
    const int wid = tid >> 5, lid = tid & 31;
    const int wm = wid >> 2;          // 0..1  (M), 64-row warp tile
    const int wn = wid & 3;           // 0..3  (N), 32-col warp tile
    const int m0 = blockIdx.x * BM;
    const int n0 = blockIdx.y * BN;

    // cp.async fill offsets: row = tid/8 (+32*i), seg = tid%8
    const int frow = tid >> 3;
    const int fseg = tid & 7;
    uint32_t fsw[4];
#pragma unroll
    for (int i = 0; i < 4; i++) fsw[i] = sw128((frow + 32 * i) * 128 + fseg * 16);

    // global induction pointers (advance by BK per chunk; row offsets fold to immediates)
    const __half* pX = g_X  + (size_t)(m0 + frow) * INF + fseg * 8;
    const __half* pW = g_Wt + (size_t)(n0 + frow) * INF + fseg * 8;

    float acc[4][4][4];
#pragma unroll
    for (int i = 0; i < 4; i++)
#pragma unroll
        for (int j = 0; j < 4; j++)
#pragma unroll
            for (int k = 0; k < 4; k++) acc[i][j][k] = 0.0f;

    // ldmatrix lane decomposition (validated mapping)
    const int la = lid & 15, sa = lid >> 4;               // A: row-in-16, k-seg
    const int lbr = (lid & 7) + ((lid >> 4) << 3);        // B: n-in-16
    const int lbs = (lid >> 3) & 1;                       // B: k-seg
    uint32_t arow[4], amask[4], brow[2], bmask[2];
#pragma unroll
    for (int t = 0; t < 4; t++) {
        arow[t] = (uint32_t)(wm * 64 + t * 16 + la) * 128;
        amask[t] = (arow[t] >> 3) & 0x70;
    }
#pragma unroll
    for (int t = 0; t < 2; t++) {
        brow[t] = (uint32_t)(wn * 32 + t * 16 + lbr) * 128;
        bmask[t] = (brow[t] >> 3) & 0x70;
    }
    const uint32_t akp = (uint32_t)(sa * 16);
    const uint32_t bkp = (uint32_t)(lbs * 16);

    const uint32_t sbase0 = sb;
    const uint32_t sbase1 = sb + STAGE_BYTES;
    const uint32_t sbase2 = sb + 2 * STAGE_BYTES;

    // ---- prologue: stages 0..NSTAGE-2 ----
#pragma unroll
    for (int s = 0; s < NSTAGE - 1; s++) {
        uint32_t ab = sb + s * STAGE_BYTES;
        uint32_t bb = ab + 16384;
#pragma unroll
        for (int i = 0; i < 4; i++) {
            cp16(ab + fsw[i], pX + (size_t)32 * i * INF + s * BK);
            cp16(bb + fsw[i], pW + (size_t)32 * i * INF + s * BK);
        }
        CP_COMMIT();
    }

    // next-chunk load pointers (chunk index c+2)
    const __half* pXn = pX + (NSTAGE - 1) * BK;
    const __half* pWn = pW + (NSTAGE - 1) * BK;

    // ---- main loop: ONE __syncthreads per chunk; unroll 3 folds stage indices ----
#pragma unroll 3
    for (int c = 0; c < NCHUNK; c++) {
        CP_WAIT(NSTAGE - 2);
        __syncthreads();   // stage c ready; all warps done computing stage (c-1)

        const uint32_t ab = (c % 3 == 0) ? sbase0 : (c % 3 == 1) ? sbase1 : sbase2;
        const uint32_t bb = ab + 16384;
        const int nc = (c + NSTAGE - 1) % 3;
        const uint32_t nab = (nc == 0) ? sbase0 : (nc == 1) ? sbase1 : sbase2;
        const uint32_t nbb = nab + 16384;
        const bool donxt = c < NCHUNK - (NSTAGE - 1);

#pragma unroll
        for (int ks = 0; ks < 4; ks++) {
            const uint32_t kA = (uint32_t)(ks * 32) + akp;
            const uint32_t kB = (uint32_t)(ks * 32) + bkp;
            uint32_t afr[4][4], bfr[4][2];

            // head: afr[0] + both B loads -> first MMA depends on 3 LDSMs, not 6
            ldmx4(afr[0][0], afr[0][1], afr[0][2], afr[0][3],
                  ab + arow[0] + (kA ^ amask[0]));
#pragma unroll
            for (int nb = 0; nb < 2; nb++) {
                uint32_t r0, r1, r2, r3;
                ldmx4(r0, r1, r2, r3, bb + brow[nb] + (kB ^ bmask[nb]));
                bfr[nb * 2 + 0][0] = r0; bfr[nb * 2 + 0][1] = r1;
                bfr[nb * 2 + 1][0] = r2; bfr[nb * 2 + 1][1] = r3;
            }
            // body: prefetch afr[mt+1] under mt's MMAs
#pragma unroll
            for (int mt = 0; mt < 4; mt++) {
                if (mt < 3)
                    ldmx4(afr[mt + 1][0], afr[mt + 1][1], afr[mt + 1][2], afr[mt + 1][3],
                          ab + arow[mt + 1] + (kA ^ amask[mt + 1]));
#pragma unroll
                for (int nt = 0; nt < 4; nt++)
                    mma16816(acc[mt][nt], afr[mt], bfr[nt]);
            }

            // after the first ks block: issue next chunk's fill (validated schedule)
            if (ks == 0) {
                if (donxt) {
#pragma unroll
                    for (int i = 0; i < 4; i++) {
                        cp16(nab + fsw[i], pXn + (size_t)32 * i * INF);
                        cp16(nbb + fsw[i], pWn + (size_t)32 * i * INF);
                    }
                }
                CP_COMMIT();
            }
        }
        pXn += BK;
        pWn += BK;
    }

    // ---- epilogue: bias-fused float2 stores ----
    const int mrow = m0 + wm * 64 + (lid >> 2);
    const int ncol = n0 + wn * 32 + (lid & 3) * 2;
#pragma unroll
    for (int mt = 0; mt < 4; mt++) {
#pragma unroll
        for (int nt = 0; nt < 4; nt++) {
            int col = ncol + nt * 8;
            float2 bb = *reinterpret_cast<const float2*>(bias + col);
            int r0 = mrow + mt * 16;
            float2 v0 = {acc[mt][nt][0] + bb.x, acc[mt][nt][1] + bb.y};
            float2 v1 = {acc[mt][nt][2] + bb.x, acc[mt][nt][3] + bb.y};
            *reinterpret_cast<float2*>(out + (size_t)r0 * OUTF + col) = v0;
            *reinterpret_cast<float2*>(out + (size_t)(r0 + 8) * OUTF + col) = v1;
        }
    }
}

// ---------------- launch ----------------
extern "C" void kernel_launch(void* const* d_in, const int* in_sizes, int n_in,
                              void* d_out, int out_size) {
    const float* x      = (const float*)d_in[0];
    const int*   qw     = (const int*)d_in[1];
    const float* scales = (const float*)d_in[2];
    const float* zeros  = (const float*)d_in[3];
    const float* bias   = (const float*)d_in[4];
    float* out = (float*)d_out;

    cudaFuncSetAttribute(gemm_kernel, cudaFuncAttributeMaxDynamicSharedMemorySize, SMEM_BYTES);

    prep_kernel<<<PREP_BLOCKS, 256>>>(x, qw, scales, zeros);
    gemm_kernel<<<dim3(MTOT / BM, OUTF / BN), 256, SMEM_BYTES>>>(bias, out);
}

// round 16
// speedup vs baseline: 1.0050x; 1.0007x over previous
#include <cuda_runtime.h>
#include <cuda_fp16.h>
#include <cstdint>
#include <cstddef>

// Problem dims
#define INF    4096
#define OUTF   11008
#define MTOT   4096     // 2*2048
#define GROUPS 32

// GEMM tiling (validated best: 128x128, 256 thr, 2 CTAs/SM)
#define BM     128
#define BN     128
#define BK     64                  // halves per stage (128B rows -> SW128 atom)
#define NCHUNK (INF / BK)          // 64
#define NSTAGE 3

#define STAGE_BYTES 32768          // 16KB A + 16KB B
#define SMEM_BYTES  (NSTAGE * STAGE_BYTES)   // 98304 -> 2 CTAs/SM

// Prep kernel grid: dequant blocks FIRST (longest-job-first), then convx
#define DEQ_BLOCKS     (OUTF / 8)  // 1376 blocks; each owns 8 n x 512 packed rows
#define CONVX_BLOCKS   4096        // 4,194,304 float4 vecs / (256 thr * 4 vec)
#define PREP_BLOCKS    (DEQ_BLOCKS + CONVX_BLOCKS)

// Scratch (static __device__ arrays; no allocation APIs used)
__device__ __align__(16) __half g_Wt[(size_t)OUTF * INF];   // W^T, [N, K] K-major f16
__device__ __align__(16) __half g_X[(size_t)MTOT * INF];    // x in f16

// ---------------- helpers ----------------
__device__ __forceinline__ uint32_t smem_u32(const void* p) {
    uint32_t a;
    asm("{ .reg .u64 t; cvta.to.shared.u64 t, %1; cvt.u32.u64 %0, t; }" : "=r"(a) : "l"(p));
    return a;
}
__device__ __forceinline__ uint32_t sw128(uint32_t off) {
    return off ^ ((off >> 3) & 0x70);
}
__device__ __forceinline__ void cp16(uint32_t dst, const void* src) {
    asm volatile("cp.async.cg.shared.global [%0], [%1], 16;" :: "r"(dst), "l"(src));
}
#define CP_COMMIT() asm volatile("cp.async.commit_group;" ::: "memory")
#define CP_WAIT(n)  asm volatile("cp.async.wait_group %0;" :: "n"(n) : "memory")

// volatile: must stay ordered vs barriers / cp.async (touches shared memory)
__device__ __forceinline__ void ldmx4(uint32_t& r0, uint32_t& r1, uint32_t& r2, uint32_t& r3,
                                      uint32_t addr) {
    asm volatile("ldmatrix.sync.aligned.m8n8.x4.shared.b16 {%0,%1,%2,%3}, [%4];"
                 : "=r"(r0), "=r"(r1), "=r"(r2), "=r"(r3) : "r"(addr));
}
// NON-volatile: pure register dataflow; ptxas may interleave MMAs with later LDSMs
__device__ __forceinline__ void mma16816(float* c, const uint32_t* a, const uint32_t* b) {
    asm("mma.sync.aligned.m16n8k16.row.col.f32.f16.f16.f32 "
        "{%0,%1,%2,%3}, {%4,%5,%6,%7}, {%8,%9}, {%0,%1,%2,%3};"
        : "+f"(c[0]), "+f"(c[1]), "+f"(c[2]), "+f"(c[3])
        : "r"(a[0]), "r"(a[1]), "r"(a[2]), "r"(a[3]), "r"(b[0]), "r"(b[1]));
}

// ---------------- Kernel 1: fused prep ----------------
// b < DEQ_BLOCKS : dequant 8-n slice of qweight -> W^T f16 (sector-perfect reads,
//                  smem transpose with pad-9 stride, coalesced writes).
//                  Heavy blocks scheduled FIRST so they overlap the convx swarm.
// else           : x fp32 -> f16, 4 float4 per thread (fewer blocks, more MLP)
__global__ void __launch_bounds__(256) prep_kernel(const float* __restrict__ x,
                                                   const int* __restrict__ qw,
                                                   const float* __restrict__ scales,
                                                   const float* __restrict__ zeros) {
    __shared__ int s[512 * 9];      // 18KB, row stride 9 ints (9 coprime 32 -> no conflicts)
    int b = blockIdx.x;
    int tid = threadIdx.x;
    if (b < DEQ_BLOCKS) {
        const int n0 = b * 8;
        // load phase: qw tile [512 rows x 8 ints], int4 per 4-int half-row
#pragma unroll
        for (int i = 0; i < 4; i++) {
            int v = tid + 256 * i;        // 0..1023
            int row = v >> 1, half = v & 1;
            int4 q4 = *reinterpret_cast<const int4*>(qw + row * OUTF + n0 + half * 4);
            int* dst = s + row * 9 + half * 4;
            dst[0] = q4.x; dst[1] = q4.y; dst[2] = q4.z; dst[3] = q4.w;
        }
        __syncthreads();
        // compute phase: warp w handles n = n0 + w; lane l handles rows l + 32j
        const int w = tid >> 5, l = tid & 31;
        const int n = n0 + w;
        const float* sc = scales + n * GROUPS;
        const float* zr = zeros + n * GROUPS;
        __half* outp = g_Wt + (size_t)n * INF;
#pragma unroll
        for (int j = 0; j < 16; j++) {
            int r = l + 32 * j;
            int q = s[r * 9 + w];
            int g = r >> 4;
            float ss = sc[g];
            float zz = zr[g];
            __half2 h[4];
#pragma unroll
            for (int jj = 0; jj < 4; jj++) {
                float v0 = (float)((q >> (8 * jj)) & 0xF) * ss - zz;
                float v1 = (float)((q >> (8 * jj + 4)) & 0xF) * ss - zz;
                h[jj] = __floats2half2_rn(v0, v1);
            }
            *reinterpret_cast<uint4*>(outp + (size_t)r * 8) = *reinterpret_cast<uint4*>(h);
        }
    } else {
        size_t base = (size_t)(b - DEQ_BLOCKS) * 1024 + tid;   // 4 vecs per thread
#pragma unroll
        for (int i = 0; i < 4; i++) {
            size_t idx = base + 256 * i;
            float4 v = reinterpret_cast<const float4*>(x)[idx];
            __half2 a = __floats2half2_rn(v.x, v.y);
            __half2 bb = __floats2half2_rn(v.z, v.w);
            uint2 u;
            u.x = *reinterpret_cast<uint32_t*>(&a);
            u.y = *reinterpret_cast<uint32_t*>(&bb);
            reinterpret_cast<uint2*>(g_X)[idx] = u;
        }
    }
}

// ---------------- Kernel 2: pipelined HMMA GEMM, 128x128x64, 3 stages, occ=2 ----------------
// (byte-identical to the validated 742.8us round-15 version)
__global__ void __launch_bounds__(256, 2) gemm_kernel(const float* __restrict__ bias,
                                                      float* __restrict__ out) {
    extern __shared__ char smem[];
    uint32_t sb = smem_u32(smem);
    const int tid = threadIdx.x;
    const int wid = tid >> 5, lid = tid & 31;
    const int wm = wid >> 2;          // 0..1  (M), 64-row warp tile
    const int wn = wid & 3;           // 0..3  (N), 32-col warp tile
    const int m0 = blockIdx.x * BM;
    const int n0 = blockIdx.y * BN;

    // cp.async fill offsets: row = tid/8 (+32*i), seg = tid%8
    const int frow = tid >> 3;
    const int fseg = tid & 7;
    uint32_t fsw[4];
#pragma unroll
    for (int i = 0; i < 4; i++) fsw[i] = sw128((frow + 32 * i) * 128 + fseg * 16);

    // global induction pointers (advance by BK per chunk; row offsets fold to immediates)
    const __half* pX = g_X  + (size_t)(m0 + frow) * INF + fseg * 8;
    const __half* pW = g_Wt + (size_t)(n0 + frow) * INF + fseg * 8;

    float acc[4][4][4];
#pragma unroll
    for (int i = 0; i < 4; i++)
#pragma unroll
        for (int j = 0; j < 4; j++)
#pragma unroll
            for (int k = 0; k < 4; k++) acc[i][j][k] = 0.0f;

    // ldmatrix lane decomposition (validated mapping)
    const int la = lid & 15, sa = lid >> 4;               // A: row-in-16, k-seg
    const int lbr = (lid & 7) + ((lid >> 4) << 3);        // B: n-in-16
    const int lbs = (lid >> 3) & 1;                       // B: k-seg
    uint32_t arow[4], amask[4], brow[2], bmask[2];
#pragma unroll
    for (int t = 0; t < 4; t++) {
        arow[t] = (uint32_t)(wm * 64 + t * 16 + la) * 128;
        amask[t] = (arow[t] >> 3) & 0x70;
    }
#pragma unroll
    for (int t = 0; t < 2; t++) {
        brow[t] = (uint32_t)(wn * 32 + t * 16 + lbr) * 128;
        bmask[t] = (brow[t] >> 3) & 0x70;
    }
    const uint32_t akp = (uint32_t)(sa * 16);
    const uint32_t bkp = (uint32_t)(lbs * 16);

    const uint32_t sbase0 = sb;
    const uint32_t sbase1 = sb + STAGE_BYTES;
    const uint32_t sbase2 = sb + 2 * STAGE_BYTES;

    // ---- prologue: stages 0..NSTAGE-2 ----
#pragma unroll
    for (int s = 0; s < NSTAGE - 1; s++) {
        uint32_t ab = sb + s * STAGE_BYTES;
        uint32_t bb = ab + 16384;
#pragma unroll
        for (int i = 0; i < 4; i++) {
            cp16(ab + fsw[i], pX + (size_t)32 * i * INF + s * BK);
            cp16(bb + fsw[i], pW + (size_t)32 * i * INF + s * BK);
        }
        CP_COMMIT();
    }

    // next-chunk load pointers (chunk index c+2)
    const __half* pXn = pX + (NSTAGE - 1) * BK;
    const __half* pWn = pW + (NSTAGE - 1) * BK;

    // ---- main loop: ONE __syncthreads per chunk; unroll 3 folds stage indices ----
#pragma unroll 3
    for (int c = 0; c < NCHUNK; c++) {
        CP_WAIT(NSTAGE - 2);
        __syncthreads();   // stage c ready; all warps done computing stage (c-1)

        const uint32_t ab = (c % 3 == 0) ? sbase0 : (c % 3 == 1) ? sbase1 : sbase2;
        const uint32_t bb = ab + 16384;
        const int nc = (c + NSTAGE - 1) % 3;
        const uint32_t nab = (nc == 0) ? sbase0 : (nc == 1) ? sbase1 : sbase2;
        const uint32_t nbb = nab + 16384;
        const bool donxt = c < NCHUNK - (NSTAGE - 1);

#pragma unroll
        for (int ks = 0; ks < 4; ks++) {
            const uint32_t kA = (uint32_t)(ks * 32) + akp;
            const uint32_t kB = (uint32_t)(ks * 32) + bkp;
            uint32_t afr[4][4], bfr[4][2];

            // head: afr[0] + both B loads -> first MMA depends on 3 LDSMs, not 6
            ldmx4(afr[0][0], afr[0][1], afr[0][2], afr[0][3],
                  ab + arow[0] + (kA ^ amask[0]));
#pragma unroll
            for (int nb = 0; nb < 2; nb++) {
                uint32_t r0, r1, r2, r3;
                ldmx4(r0, r1, r2, r3, bb + brow[nb] + (kB ^ bmask[nb]));
                bfr[nb * 2 + 0][0] = r0; bfr[nb * 2 + 0][1] = r1;
                bfr[nb * 2 + 1][0] = r2; bfr[nb * 2 + 1][1] = r3;
            }
            // body: prefetch afr[mt+1] under mt's MMAs
#pragma unroll
            for (int mt = 0; mt < 4; mt++) {
                if (mt < 3)
                    ldmx4(afr[mt + 1][0], afr[mt + 1][1], afr[mt + 1][2], afr[mt + 1][3],
                          ab + arow[mt + 1] + (kA ^ amask[mt + 1]));
#pragma unroll
                for (int nt = 0; nt < 4; nt++)
                    mma16816(acc[mt][nt], afr[mt], bfr[nt]);
            }

            // after the first ks block: issue next chunk's fill (validated schedule)
            if (ks == 0) {
                if (donxt) {
#pragma unroll
                    for (int i = 0; i < 4; i++) {
                        cp16(nab + fsw[i], pXn + (size_t)32 * i * INF);
                        cp16(nbb + fsw[i], pWn + (size_t)32 * i * INF);
                    }
                }
                CP_COMMIT();
            }
        }
        pXn += BK;
        pWn += BK;
    }

    // ---- epilogue: bias-fused float2 stores ----
    const int mrow = m0 + wm * 64 + (lid >> 2);
    const int ncol = n0 + wn * 32 + (lid & 3) * 2;
#pragma unroll
    for (int mt = 0; mt < 4; mt++) {
#pragma unroll
        for (int nt = 0; nt < 4; nt++) {
            int col = ncol + nt * 8;
            float2 bb = *reinterpret_cast<const float2*>(bias + col);
            int r0 = mrow + mt * 16;
            float2 v0 = {acc[mt][nt][0] + bb.x, acc[mt][nt][1] + bb.y};
            float2 v1 = {acc[mt][nt][2] + bb.x, acc[mt][nt][3] + bb.y};
            *reinterpret_cast<float2*>(out + (size_t)r0 * OUTF + col) = v0;
            *reinterpret_cast<float2*>(out + (size_t)(r0 + 8) * OUTF + col) = v1;
        }
    }
}

// ---------------- launch ----------------
extern "C" void kernel_launch(void* const* d_in, const int* in_sizes, int n_in,
                              void* d_out, int out_size) {
    const float* x      = (const float*)d_in[0];
    const int*   qw     = (const int*)d_in[1];
    const float* scales = (const float*)d_in[2];
    const float* zeros  = (const float*)d_in[3];
    const float* bias   = (const float*)d_in[4];
    float* out = (float*)d_out;

    cudaFuncSetAttribute(gemm_kernel, cudaFuncAttributeMaxDynamicSharedMemorySize, SMEM_BYTES);

    prep_kernel<<<PREP_BLOCKS, 256>>>(x, qw, scales, zeros);
    gemm_kernel<<<dim3(MTOT / BM, OUTF / BN), 256, SMEM_BYTES>>>(bias, out);
}

// round 17
// speedup vs baseline: 1.0053x; 1.0002x over previous
#include <cuda_runtime.h>
#include <cuda_fp16.h>
#include <cstdint>
#include <cstddef>

// Problem dims
#define INF    4096
#define OUTF   11008
#define MTOT   4096     // 2*2048
#define GROUPS 32

// GEMM tiling (validated best: 128x128, 256 thr, 2 CTAs/SM)
#define BM     128
#define BN     128
#define BK     64                  // halves per stage (128B rows -> SW128 atom)
#define NCHUNK (INF / BK)          // 64
#define NSTAGE 3

#define STAGE_BYTES 32768          // 16KB A + 16KB B
#define SMEM_BYTES  (NSTAGE * STAGE_BYTES)   // 98304 -> 2 CTAs/SM

// Prep kernel grid: dequant blocks FIRST (longest-job-first), then convx
#define DEQ_BLOCKS     (OUTF / 8)  // 1376 blocks; each owns 8 n x 512 packed rows
#define CONVX_BLOCKS   4096        // 4,194,304 float4 vecs / (256 thr * 4 vec)
#define PREP_BLOCKS    (DEQ_BLOCKS + CONVX_BLOCKS)

// Scratch (static __device__ arrays; no allocation APIs used)
__device__ __align__(16) __half g_Wt[(size_t)OUTF * INF];   // W^T, [N, K] K-major f16
__device__ __align__(16) __half g_X[(size_t)MTOT * INF];    // x in f16

// ---------------- helpers ----------------
__device__ __forceinline__ uint32_t smem_u32(const void* p) {
    uint32_t a;
    asm("{ .reg .u64 t; cvta.to.shared.u64 t, %1; cvt.u32.u64 %0, t; }" : "=r"(a) : "l"(p));
    return a;
}
__device__ __forceinline__ uint32_t sw128(uint32_t off) {
    return off ^ ((off >> 3) & 0x70);
}
__device__ __forceinline__ void cp16(uint32_t dst, const void* src) {
    asm volatile("cp.async.cg.shared.global [%0], [%1], 16;" :: "r"(dst), "l"(src));
}
#define CP_COMMIT() asm volatile("cp.async.commit_group;" ::: "memory")
#define CP_WAIT(n)  asm volatile("cp.async.wait_group %0;" :: "n"(n) : "memory")

// volatile: must stay ordered vs barriers / cp.async (touches shared memory)
__device__ __forceinline__ void ldmx4(uint32_t& r0, uint32_t& r1, uint32_t& r2, uint32_t& r3,
                                      uint32_t addr) {
    asm volatile("ldmatrix.sync.aligned.m8n8.x4.shared.b16 {%0,%1,%2,%3}, [%4];"
                 : "=r"(r0), "=r"(r1), "=r"(r2), "=r"(r3) : "r"(addr));
}
// NON-volatile: pure register dataflow; ptxas may interleave MMAs with later LDSMs
__device__ __forceinline__ void mma16816(float* c, const uint32_t* a, const uint32_t* b) {
    asm("mma.sync.aligned.m16n8k16.row.col.f32.f16.f16.f32 "
        "{%0,%1,%2,%3}, {%4,%5,%6,%7}, {%8,%9}, {%0,%1,%2,%3};"
        : "+f"(c[0]), "+f"(c[1]), "+f"(c[2]), "+f"(c[3])
        : "r"(a[0]), "r"(a[1]), "r"(a[2]), "r"(a[3]), "r"(b[0]), "r"(b[1]));
}

// ---------------- Kernel 1: fused prep ----------------
// b < DEQ_BLOCKS : dequant 8-n slice of qweight -> W^T f16 (sector-perfect reads,
//                  smem transpose with pad-9 stride, coalesced writes).
//                  Heavy blocks scheduled FIRST so they overlap the convx swarm.
// else           : x fp32 -> f16, 4 float4 per thread (fewer blocks, more MLP)
__global__ void __launch_bounds__(256) prep_kernel(const float* __restrict__ x,
                                                   const int* __restrict__ qw,
                                                   const float* __restrict__ scales,
                                                   const float* __restrict__ zeros) {
    __shared__ int s[512 * 9];      // 18KB, row stride 9 ints (9 coprime 32 -> no conflicts)
    int b = blockIdx.x;
    int tid = threadIdx.x;
    if (b < DEQ_BLOCKS) {
        const int n0 = b * 8;
        // load phase: qw tile [512 rows x 8 ints], int4 per 4-int half-row
#pragma unroll
        for (int i = 0; i < 4; i++) {
            int v = tid + 256 * i;        // 0..1023
            int row = v >> 1, half = v & 1;
            int4 q4 = *reinterpret_cast<const int4*>(qw + row * OUTF + n0 + half * 4);
            int* dst = s + row * 9 + half * 4;
            dst[0] = q4.x; dst[1] = q4.y; dst[2] = q4.z; dst[3] = q4.w;
        }
        __syncthreads();
        // compute phase: warp w handles n = n0 + w; lane l handles rows l + 32j
        const int w = tid >> 5, l = tid & 31;
        const int n = n0 + w;
        const float* sc = scales + n * GROUPS;
        const float* zr = zeros + n * GROUPS;
        __half* outp = g_Wt + (size_t)n * INF;
#pragma unroll
        for (int j = 0; j < 16; j++) {
            int r = l + 32 * j;
            int q = s[r * 9 + w];
            int g = r >> 4;
            float ss = sc[g];
            float zz = zr[g];
            __half2 h[4];
#pragma unroll
            for (int jj = 0; jj < 4; jj++) {
                float v0 = (float)((q >> (8 * jj)) & 0xF) * ss - zz;
                float v1 = (float)((q >> (8 * jj + 4)) & 0xF) * ss - zz;
                h[jj] = __floats2half2_rn(v0, v1);
            }
            *reinterpret_cast<uint4*>(outp + (size_t)r * 8) = *reinterpret_cast<uint4*>(h);
        }
    } else {
        size_t base = (size_t)(b - DEQ_BLOCKS) * 1024 + tid;   // 4 vecs per thread
#pragma unroll
        for (int i = 0; i < 4; i++) {
            size_t idx = base + 256 * i;
            float4 v = reinterpret_cast<const float4*>(x)[idx];
            __half2 a = __floats2half2_rn(v.x, v.y);
            __half2 bb = __floats2half2_rn(v.z, v.w);
            uint2 u;
            u.x = *reinterpret_cast<uint32_t*>(&a);
            u.y = *reinterpret_cast<uint32_t*>(&bb);
            reinterpret_cast<uint2*>(g_X)[idx] = u;
        }
    }
}

// ---------------- Kernel 2: pipelined HMMA GEMM, 128x128x64, 3 stages, occ=2 ----------------
// Mainloop byte-identical to the validated 742.8-746us configuration; epilogue
// bias loads hoisted (nt-outer) to drop the 4x-redundant LDGs at the tail.
__global__ void __launch_bounds__(256, 2) gemm_kernel(const float* __restrict__ bias,
                                                      float* __restrict__ out) {
    extern __shared__ char smem[];
    uint32_t sb = smem_u32(smem);
    const int tid = threadIdx.x;
    const int wid = tid >> 5, lid = tid & 31;
    const int wm = wid >> 2;          // 0..1  (M), 64-row warp tile
    const int wn = wid & 3;           // 0..3  (N), 32-col warp tile
    const int m0 = blockIdx.x * BM;
    const int n0 = blockIdx.y * BN;

    // cp.async fill offsets: row = tid/8 (+32*i), seg = tid%8
    const int frow = tid >> 3;
    const int fseg = tid & 7;
    uint32_t fsw[4];
#pragma unroll
    for (int i = 0; i < 4; i++) fsw[i] = sw128((frow + 32 * i) * 128 + fseg * 16);

    // global induction pointers (advance by BK per chunk; row offsets fold to immediates)
    const __half* pX = g_X  + (size_t)(m0 + frow) * INF + fseg * 8;
    const __half* pW = g_Wt + (size_t)(n0 + frow) * INF + fseg * 8;

    float acc[4][4][4];
#pragma unroll
    for (int i = 0; i < 4; i++)
#pragma unroll
        for (int j = 0; j < 4; j++)
#pragma unroll
            for (int k = 0; k < 4; k++) acc[i][j][k] = 0.0f;

    // ldmatrix lane decomposition (validated mapping)
    const int la = lid & 15, sa = lid >> 4;               // A: row-in-16, k-seg
    const int lbr = (lid & 7) + ((lid >> 4) << 3);        // B: n-in-16
    const int lbs = (lid >> 3) & 1;                       // B: k-seg
    uint32_t arow[4], amask[4], brow[2], bmask[2];
#pragma unroll
    for (int t = 0; t < 4; t++) {
        arow[t] = (uint32_t)(wm * 64 + t * 16 + la) * 128;
        amask[t] = (arow[t] >> 3) & 0x70;
    }
#pragma unroll
    for (int t = 0; t < 2; t++) {
        brow[t] = (uint32_t)(wn * 32 + t * 16 + lbr) * 128;
        bmask[t] = (brow[t] >> 3) & 0x70;
    }
    const uint32_t akp = (uint32_t)(sa * 16);
    const uint32_t bkp = (uint32_t)(lbs * 16);

    const uint32_t sbase0 = sb;
    const uint32_t sbase1 = sb + STAGE_BYTES;
    const uint32_t sbase2 = sb + 2 * STAGE_BYTES;

    // ---- prologue: stages 0..NSTAGE-2 ----
#pragma unroll
    for (int s = 0; s < NSTAGE - 1; s++) {
        uint32_t ab = sb + s * STAGE_BYTES;
        uint32_t bb = ab + 16384;
#pragma unroll
        for (int i = 0; i < 4; i++) {
            cp16(ab + fsw[i], pX + (size_t)32 * i * INF + s * BK);
            cp16(bb + fsw[i], pW + (size_t)32 * i * INF + s * BK);
        }
        CP_COMMIT();
    }

    // next-chunk load pointers (chunk index c+2)
    const __half* pXn = pX + (NSTAGE - 1) * BK;
    const __half* pWn = pW + (NSTAGE - 1) * BK;

    // ---- main loop: ONE __syncthreads per chunk; unroll 3 folds stage indices ----
#pragma unroll 3
    for (int c = 0; c < NCHUNK; c++) {
        CP_WAIT(NSTAGE - 2);
        __syncthreads();   // stage c ready; all warps done computing stage (c-1)

        const uint32_t ab = (c % 3 == 0) ? sbase0 : (c % 3 == 1) ? sbase1 : sbase2;
        const uint32_t bb = ab + 16384;
        const int nc = (c + NSTAGE - 1) % 3;
        const uint32_t nab = (nc == 0) ? sbase0 : (nc == 1) ? sbase1 : sbase2;
        const uint32_t nbb = nab + 16384;
        const bool donxt = c < NCHUNK - (NSTAGE - 1);

#pragma unroll
        for (int ks = 0; ks < 4; ks++) {
            const uint32_t kA = (uint32_t)(ks * 32) + akp;
            const uint32_t kB = (uint32_t)(ks * 32) + bkp;
            uint32_t afr[4][4], bfr[4][2];

            // head: afr[0] + both B loads -> first MMA depends on 3 LDSMs, not 6
            ldmx4(afr[0][0], afr[0][1], afr[0][2], afr[0][3],
                  ab + arow[0] + (kA ^ amask[0]));
#pragma unroll
            for (int nb = 0; nb < 2; nb++) {
                uint32_t r0, r1, r2, r3;
                ldmx4(r0, r1, r2, r3, bb + brow[nb] + (kB ^ bmask[nb]));
                bfr[nb * 2 + 0][0] = r0; bfr[nb * 2 + 0][1] = r1;
                bfr[nb * 2 + 1][0] = r2; bfr[nb * 2 + 1][1] = r3;
            }
            // body: prefetch afr[mt+1] under mt's MMAs
#pragma unroll
            for (int mt = 0; mt < 4; mt++) {
                if (mt < 3)
                    ldmx4(afr[mt + 1][0], afr[mt + 1][1], afr[mt + 1][2], afr[mt + 1][3],
                          ab + arow[mt + 1] + (kA ^ amask[mt + 1]));
#pragma unroll
                for (int nt = 0; nt < 4; nt++)
                    mma16816(acc[mt][nt], afr[mt], bfr[nt]);
            }

            // after the first ks block: issue next chunk's fill (validated schedule)
            if (ks == 0) {
                if (donxt) {
#pragma unroll
                    for (int i = 0; i < 4; i++) {
                        cp16(nab + fsw[i], pXn + (size_t)32 * i * INF);
                        cp16(nbb + fsw[i], pWn + (size_t)32 * i * INF);
                    }
                }
                CP_COMMIT();
            }
        }
        pXn += BK;
        pWn += BK;
    }

    // ---- epilogue: bias-fused float2 stores (bias hoisted: one load per nt) ----
    const int mrow = m0 + wm * 64 + (lid >> 2);
    const int ncol = n0 + wn * 32 + (lid & 3) * 2;
#pragma unroll
    for (int nt = 0; nt < 4; nt++) {
        const int col = ncol + nt * 8;
        const float2 bb = *reinterpret_cast<const float2*>(bias + col);
#pragma unroll
        for (int mt = 0; mt < 4; mt++) {
            int r0 = mrow + mt * 16;
            float2 v0 = {acc[mt][nt][0] + bb.x, acc[mt][nt][1] + bb.y};
            float2 v1 = {acc[mt][nt][2] + bb.x, acc[mt][nt][3] + bb.y};
            *reinterpret_cast<float2*>(out + (size_t)r0 * OUTF + col) = v0;
            *reinterpret_cast<float2*>(out + (size_t)(r0 + 8) * OUTF + col) = v1;
        }
    }
}

// ---------------- launch ----------------
extern "C" void kernel_launch(void* const* d_in, const int* in_sizes, int n_in,
                              void* d_out, int out_size) {
    const float* x      = (const float*)d_in[0];
    const int*   qw     = (const int*)d_in[1];
    const float* scales = (const float*)d_in[2];
    const float* zeros  = (const float*)d_in[3];
    const float* bias   = (const float*)d_in[4];
    float* out = (float*)d_out;

    cudaFuncSetAttribute(gemm_kernel, cudaFuncAttributeMaxDynamicSharedMemorySize, SMEM_BYTES);

    prep_kernel<<<PREP_BLOCKS, 256>>>(x, qw, scales, zeros);
    gemm_kernel<<<dim3(MTOT / BM, OUTF / BN), 256, SMEM_BYTES>>>(bias, out);
}